// round 14
// baseline (speedup 1.0000x reference)
#include <cuda_runtime.h>
#include <cstdint>

// NolinerSEM: per-expert MLP. out[b,e] = leaky(dot(leaky(W1[e]@x[b,e,:]+b1[e]), W2[e]) + b2[e])
// B=32768, E=90, H=32.
//
// R13: smem-crossbar diet. (1) B fragments for ksteps 0..5 hoisted into 24 regs,
// loaded ONCE per CTA (B is tile-invariant) -> per-tile LDS bytes -25%.
// (2) Mid-epilogue full-CTA sync replaced by pairwise named barrier (the two
// warps sharing rows). Pipeline/staging structure unchanged from R9.

namespace {
constexpr int Ee  = 90;
constexpr int Hh  = 32;
constexpr int STR = 104;   // floats; LDS.64 conflict-free
constexpr int MT  = 64;    // rows per tile
constexpr int T   = 8;     // tiles per CTA
constexpr int KSTEPS = 12; // K padded 90 -> 96
constexpr int KH  = 6;     // ksteps with hoisted B
constexpr int THREADS = 256;
constexpr float NEG = 0.33f;
constexpr int XBUF = MT * STR;  // floats per X buffer
}

__device__ __forceinline__ uint32_t f2tf32(float x) {
    uint32_t u;
    asm("cvt.rna.tf32.f32 %0, %1;" : "=r"(u) : "f"(x));
    return u;
}

__device__ __forceinline__ float lk(float v) { return v >= 0.f ? v : NEG * v; }

__device__ __forceinline__ uint32_t smem_u32(const void* p) {
    uint32_t a;
    asm("{ .reg .u64 t; cvta.to.shared.u64 t, %1; cvt.u32.u64 %0, t; }" : "=r"(a) : "l"(p));
    return a;
}

__device__ __forceinline__ void cpasync8(uint32_t saddr, const void* g) {
    asm volatile("cp.async.ca.shared.global [%0], [%1], 8;" :: "r"(saddr), "l"(g));
}

__device__ __forceinline__ void mma8(float c[4], const uint32_t a[4], uint32_t b0, uint32_t b1) {
    asm volatile(
        "mma.sync.aligned.m16n8k8.row.col.f32.tf32.tf32.f32 "
        "{%0,%1,%2,%3}, {%4,%5,%6,%7}, {%8,%9}, {%0,%1,%2,%3};"
        : "+f"(c[0]), "+f"(c[1]), "+f"(c[2]), "+f"(c[3])
        : "r"(a[0]), "r"(a[1]), "r"(a[2]), "r"(a[3]), "r"(b0), "r"(b1));
}

__global__ void __launch_bounds__(THREADS, 3) sem_kernel(
    const float* __restrict__ x, const float* __restrict__ W1,
    const float* __restrict__ b1, const float* __restrict__ W2,
    const float* __restrict__ b2, float* __restrict__ out, int G)
{
    extern __shared__ float smem[];
    float* Xs   = smem;                 // [2][MT][STR] raw fp32
    float* Ws   = Xs + 2 * XBUF;        // [Hh][STR] tf32 bits, natural [n][k]
    float* b1s  = Ws + Hh * STR;        // [32]
    float* w2s  = b1s + Hh;             // [32]
    float* part = w2s + Hh;             // [MT] layer-2 partials (n-half 1)

    const int e    = blockIdx.x / G;
    const int grp  = blockIdx.x - e * G;
    const int row0 = grp * (MT * T);
    const int tid  = threadIdx.x;
    const int lane = tid & 31;
    const int w    = tid >> 5;
    const uint32_t xsBase = smem_u32(Xs);

    // ---- tile staging: warp w stages rows {w, w+8, ...} of tile t_idx; div-free ----
    auto stage = [&](int t_idx) {
        const int buf = t_idx & 1;
        const float* xRow = x + (size_t)(row0 + t_idx * MT + w) * (Ee * Ee) + e * Ee;
        uint32_t sRow = xsBase + (uint32_t)(buf * XBUF + w * STR) * 4u;
        #pragma unroll 1
        for (int i = 0; i < MT / 8; ++i) {
            cpasync8(sRow + (uint32_t)lane * 8u, xRow + lane * 2);           // cols 0..63
            if (lane < 13)
                cpasync8(sRow + (32u + lane) * 8u, xRow + 64 + lane * 2);    // cols 64..89
            xRow += 8 * (Ee * Ee);
            sRow += 8u * STR * 4u;
        }
    };

    // ---- prologue: stage tile 0, W1, biases; zero-pad cols 90..95 of both buffers ----
    stage(0);
    asm volatile("cp.async.commit_group;");

    {   // W1[e]: warp w stages n = {w, w+8, w+16, w+24}; vectorized, div-free
        const float* wRow = W1 + (size_t)e * (Hh * Ee) + w * Ee;
        uint32_t* wsRow = (uint32_t*)(Ws + w * STR);
        #pragma unroll
        for (int j = 0; j < 4; ++j) {
            float2 v = *(const float2*)(wRow + lane * 2);
            ((uint2*)wsRow)[lane] = make_uint2(f2tf32(v.x), f2tf32(v.y));
            if (lane < 13) {
                float2 v2 = *(const float2*)(wRow + 64 + lane * 2);
                *(uint2*)(wsRow + 64 + lane * 2) = make_uint2(f2tf32(v2.x), f2tf32(v2.y));
            } else if (lane < 16) {
                *(uint2*)(wsRow + 64 + lane * 2) = make_uint2(0u, 0u);       // pad 90..95
            }
            wRow  += 8 * Ee;
            wsRow += 8 * STR;
        }
    }
    if (tid < Hh) {
        b1s[tid] = b1[e * Hh + tid];
        w2s[tid] = W2[e * Hh + tid];
    }
    for (int idx = tid; idx < 2 * MT; idx += THREADS) {                      // X pads (one-time)
        float* zp = Xs + (idx >> 6) * XBUF + (idx & (MT - 1)) * STR + 90;
        #pragma unroll
        for (int j = 0; j < 3; ++j) ((float2*)zp)[j] = make_float2(0.f, 0.f);
    }
    const float bias2 = b2[e];

    __syncthreads();   // W1/b/w2 STS visible to everyone (tile-0 cp.async still in flight)

    // ---- warp roles: wm = m-tile (16 rows), wn = n-half (16 cols) ----
    const int g = lane >> 2, t = lane & 3;
    const int wm = w & 3, wn = w >> 2;
    const uint32_t* bBase = (const uint32_t*)Ws + (wn * 16 + g) * STR + 2 * t;

    // ---- hoist B fragments for ksteps 0..KH-1 (tile-invariant): 24 regs ----
    uint2 Bh[2][KH];
    #pragma unroll
    for (int nl = 0; nl < 2; ++nl)
        #pragma unroll
        for (int ks = 0; ks < KH; ++ks)
            Bh[nl][ks] = *(const uint2*)(bBase + nl * 8 * STR + ks * 8);

    // ---- pipelined tile loop ----
    #pragma unroll 1
    for (int i = 0; i < T; ++i) {
        if (i + 1 < T) {
            stage(i + 1);
            asm volatile("cp.async.commit_group;");
            asm volatile("cp.async.wait_group 1;");   // tile i complete; i+1 in flight
        } else {
            asm volatile("cp.async.wait_group 0;");
        }
        __syncthreads();   // tile i visible; also fences part[] reuse across tiles

        // -- compute: 16(m) x 16(n) per warp over K=96; A LDS.64, B regs/LDS.64 --
        const float* aRow0 = Xs + (i & 1) * XBUF + (wm * 16 + g) * STR + 2 * t;
        const float* aRow1 = aRow0 + 8 * STR;
        float c[2][4];
        #pragma unroll
        for (int nl = 0; nl < 2; ++nl)
            #pragma unroll
            for (int j = 0; j < 4; ++j) c[nl][j] = 0.f;

        #pragma unroll
        for (int ks = 0; ks < KSTEPS; ++ks) {
            const int kb = ks * 8;
            float2 A0 = *(const float2*)(aRow0 + kb);
            float2 A1 = *(const float2*)(aRow1 + kb);
            uint32_t a[4];
            a[0] = f2tf32(A0.x);   // slot k=t    <- natural col 8ks+2t
            a[1] = f2tf32(A1.x);
            a[2] = f2tf32(A0.y);   // slot k=t+4  <- natural col 8ks+2t+1
            a[3] = f2tf32(A1.y);
            if (ks < KH) {
                #pragma unroll
                for (int nl = 0; nl < 2; ++nl)
                    mma8(c[nl], a, Bh[nl][ks].x, Bh[nl][ks].y);
            } else {
                #pragma unroll
                for (int nl = 0; nl < 2; ++nl) {
                    uint2 B = *(const uint2*)(bBase + nl * 8 * STR + kb);
                    mma8(c[nl], a, B.x, B.y);
                }
            }
        }

        // -- epilogue: leaky(c+b1) . w2 over this warp's 16 cols -> quad reduce --
        float p0 = 0.f, p1 = 0.f;      // rows g, g+8
        #pragma unroll
        for (int nl = 0; nl < 2; ++nl) {
            const int c0 = (wn * 2 + nl) * 8 + 2 * t;
            const float bb0 = b1s[c0], bb1 = b1s[c0 + 1];
            const float ww0 = w2s[c0], ww1 = w2s[c0 + 1];
            p0 += lk(c[nl][0] + bb0) * ww0 + lk(c[nl][1] + bb1) * ww1;
            p1 += lk(c[nl][2] + bb0) * ww0 + lk(c[nl][3] + bb1) * ww1;
        }
        p0 += __shfl_xor_sync(0xffffffffu, p0, 1);
        p0 += __shfl_xor_sync(0xffffffffu, p0, 2);
        p1 += __shfl_xor_sync(0xffffffffu, p1, 1);
        p1 += __shfl_xor_sync(0xffffffffu, p1, 2);

        if (t == 0 && wn == 1) {
            part[wm * 16 + g]     = p0;
            part[wm * 16 + 8 + g] = p1;
        }
        // pairwise handoff: only warps (wm, wn=0) and (wm, wn=1) need ordering.
        asm volatile("bar.sync %0, 64;" :: "r"(wm + 1) : "memory");
        if (t == 0 && wn == 0) {
            const int r = row0 + i * MT + wm * 16 + g;
            out[(size_t)r * Ee + e]       = lk(p0 + part[wm * 16 + g]     + bias2);
            out[(size_t)(r + 8) * Ee + e] = lk(p1 + part[wm * 16 + 8 + g] + bias2);
        }
    }
}

extern "C" void kernel_launch(void* const* d_in, const int* in_sizes, int n_in,
                              void* d_out, int out_size) {
    const float* x  = (const float*)d_in[0];
    const float* W1 = (const float*)d_in[1];
    const float* b1 = (const float*)d_in[2];
    const float* W2 = (const float*)d_in[3];
    const float* b2 = (const float*)d_in[4];
    float* out = (float*)d_out;

    const int B = in_sizes[0] / (Ee * Ee);           // 32768
    const int G = B / (MT * T);                      // 64 row-groups per expert
    const int grid = Ee * G;                         // 5760 CTAs
    const size_t smem = (size_t)(2 * XBUF + Hh * STR + 2 * Hh + MT) * sizeof(float); // 67072 B

    cudaFuncSetAttribute(sem_kernel, cudaFuncAttributeMaxDynamicSharedMemorySize, (int)smem);
    sem_kernel<<<grid, THREADS, smem>>>(x, W1, b1, W2, b2, out, G);
}

// round 16
// speedup vs baseline: 1.7634x; 1.7634x over previous
#include <cuda_runtime.h>
#include <cstdint>

// NolinerSEM: per-expert MLP. out[b,e] = leaky(dot(leaky(W1[e]@x[b,e,:]+b1[e]), W2[e]) + b2[e])
// B=32768, E=90, H=32.
//
// R15 = R14 with the smem race fixed. R14 zeroed X cols 90..97, racing the
// in-flight tile-0 cp.async which writes cols 0..91 (odd-e rows carry REAL data
// in cols 90,91). LDGSTS-data vs later-STS order is unguaranteed -> L2-resident
// rows got clobbered (rel_err 4.2e-2). Fix: zero ONLY cols 92..97 (disjoint
// from all cp.async writes). Cols 90,91 need no zeroing: even-e garbage there
// is killed by the zero W1 pad (B=0 at k>=90); odd-e data there is real.
// Kept from R14: 16B cp.async.cg staging (23 ops/row), e-fast grid order,
// 8B-shifted copy window + shifted A pointers for odd e.

namespace {
constexpr int Ee  = 90;
constexpr int Hh  = 32;
constexpr int STR = 104;   // floats; LDS.64 conflict-free per half-warp phase
constexpr int MT  = 64;    // rows per tile
constexpr int T   = 8;     // tiles per CTA
constexpr int KSTEPS = 12; // K padded 90 -> 96
constexpr int THREADS = 256;
constexpr float NEG = 0.33f;
constexpr int XBUF = MT * STR;  // floats per X buffer
}

__device__ __forceinline__ uint32_t f2tf32(float x) {
    uint32_t u;
    asm("cvt.rna.tf32.f32 %0, %1;" : "=r"(u) : "f"(x));
    return u;
}

__device__ __forceinline__ float lk(float v) { return v >= 0.f ? v : NEG * v; }

__device__ __forceinline__ uint32_t smem_u32(const void* p) {
    uint32_t a;
    asm("{ .reg .u64 t; cvta.to.shared.u64 t, %1; cvt.u32.u64 %0, t; }" : "=r"(a) : "l"(p));
    return a;
}

__device__ __forceinline__ void cpasync16(uint32_t saddr, const void* g) {
    asm volatile("cp.async.cg.shared.global [%0], [%1], 16;" :: "r"(saddr), "l"(g));
}

__device__ __forceinline__ void mma8(float c[4], const uint32_t a[4], uint32_t b0, uint32_t b1) {
    asm volatile(
        "mma.sync.aligned.m16n8k8.row.col.f32.tf32.tf32.f32 "
        "{%0,%1,%2,%3}, {%4,%5,%6,%7}, {%8,%9}, {%0,%1,%2,%3};"
        : "+f"(c[0]), "+f"(c[1]), "+f"(c[2]), "+f"(c[3])
        : "r"(a[0]), "r"(a[1]), "r"(a[2]), "r"(a[3]), "r"(b0), "r"(b1));
}

__global__ void __launch_bounds__(THREADS, 3) sem_kernel(
    const float* __restrict__ x, const float* __restrict__ W1,
    const float* __restrict__ b1, const float* __restrict__ W2,
    const float* __restrict__ b2, float* __restrict__ out)
{
    extern __shared__ float smem[];
    float* Xs   = smem;                 // [2][MT][STR] raw fp32 (shifted by sh for odd e)
    float* Ws   = Xs + 2 * XBUF;        // [Hh][STR] tf32 bits, natural [n][k]
    float* b1s  = Ws + Hh * STR;        // [32]
    float* w2s  = b1s + Hh;             // [32]
    float* part = w2s + Hh;             // [MT] layer-2 partials (n-half 1)

    const int e    = blockIdx.x % Ee;       // e-fast: out-line writers co-resident
    const int grp  = blockIdx.x / Ee;
    const int row0 = grp * (MT * T);
    const int tid  = threadIdx.x;
    const int lane = tid & 31;
    const int w    = tid >> 5;
    const int sh   = (e & 1) ? 2 : 0;       // smem col shift for odd-e copy window
    const uint32_t xsBase = smem_u32(Xs);

    // ---- tile staging: warp w stages rows {w, w+8, ...}; 23 x 16B cp.async.cg ----
    // Copy window = row start - sh*4 bytes (16B aligned), 368B -> smem cols 0..91.
    auto stage = [&](int t_idx) {
        const int buf = t_idx & 1;
        const float* xRow = x + (size_t)(row0 + t_idx * MT + w) * (Ee * Ee) + e * Ee - sh;
        uint32_t sRow = xsBase + (uint32_t)(buf * XBUF + w * STR) * 4u;
        #pragma unroll 1
        for (int i = 0; i < MT / 8; ++i) {
            if (lane < 23)
                cpasync16(sRow + (uint32_t)lane * 16u, xRow + lane * 4);
            xRow += 8 * (Ee * Ee);
            sRow += 8u * STR * 4u;
        }
    };

    // ---- prologue: stage tile 0, W1, biases; zero smem cols 92..97 only ----
    stage(0);
    asm volatile("cp.async.commit_group;");

    {   // W1[e]: warp w stages n = {w, w+8, w+16, w+24}; vectorized, div-free
        const float* wRow = W1 + (size_t)e * (Hh * Ee) + w * Ee;
        uint32_t* wsRow = (uint32_t*)(Ws + w * STR);
        #pragma unroll
        for (int j = 0; j < 4; ++j) {
            float2 v = *(const float2*)(wRow + lane * 2);
            ((uint2*)wsRow)[lane] = make_uint2(f2tf32(v.x), f2tf32(v.y));
            if (lane < 13) {
                float2 v2 = *(const float2*)(wRow + 64 + lane * 2);
                *(uint2*)(wsRow + 64 + lane * 2) = make_uint2(f2tf32(v2.x), f2tf32(v2.y));
            } else if (lane < 16) {
                *(uint2*)(wsRow + 64 + lane * 2) = make_uint2(0u, 0u);       // W1 pad 90..95 = 0
            }
            wRow  += 8 * Ee;
            wsRow += 8 * STR;
        }
    }
    if (tid < Hh) {
        b1s[tid] = b1[e * Hh + tid];
        w2s[tid] = W2[e * Hh + tid];
    }
    // zero X smem cols 92..97 of both buffers. cp.async NEVER writes cols >= 92,
    // so this cannot race the in-flight tile-0 staging. (Cols 90,91: real data
    // for odd e; for even e, garbage killed by the zero W1 pad at k=90,91.)
    for (int idx = tid; idx < 2 * MT; idx += THREADS) {
        float* zp = Xs + (idx >> 6) * XBUF + (idx & (MT - 1)) * STR + 92;
        #pragma unroll
        for (int j = 0; j < 3; ++j) ((float2*)zp)[j] = make_float2(0.f, 0.f);
    }
    const float bias2 = b2[e];

    // ---- warp roles: wm = m-tile (16 rows), wn = n-half (16 cols) ----
    const int g = lane >> 2, t = lane & 3;
    const int wm = w & 3, wn = w >> 2;
    const uint32_t* bBase = (const uint32_t*)Ws + (wn * 16 + g) * STR + 2 * t;

    // ---- pipelined tile loop ----
    #pragma unroll 1
    for (int i = 0; i < T; ++i) {
        if (i + 1 < T) {
            stage(i + 1);
            asm volatile("cp.async.commit_group;");
            asm volatile("cp.async.wait_group 1;");   // tile i complete; i+1 in flight
        } else {
            asm volatile("cp.async.wait_group 0;");
        }
        __syncthreads();   // tile i visible (also fences prologue STS / part[] reuse)

        // -- compute: 16(m) x 16(n) per warp over K=96; all fragment loads LDS.64 --
        const float* aRow0 = Xs + (i & 1) * XBUF + (wm * 16 + g) * STR + 2 * t + sh;
        const float* aRow1 = aRow0 + 8 * STR;
        float c[2][4];
        #pragma unroll
        for (int nl = 0; nl < 2; ++nl)
            #pragma unroll
            for (int j = 0; j < 4; ++j) c[nl][j] = 0.f;

        #pragma unroll
        for (int ks = 0; ks < KSTEPS; ++ks) {
            const int kb = ks * 8;
            float2 A0 = *(const float2*)(aRow0 + kb);
            float2 A1 = *(const float2*)(aRow1 + kb);
            uint32_t a[4];
            a[0] = f2tf32(A0.x);   // slot k=t    <- natural col 8ks+2t
            a[1] = f2tf32(A1.x);
            a[2] = f2tf32(A0.y);   // slot k=t+4  <- natural col 8ks+2t+1
            a[3] = f2tf32(A1.y);
            #pragma unroll
            for (int nl = 0; nl < 2; ++nl) {
                uint2 B = *(const uint2*)(bBase + nl * 8 * STR + kb);
                mma8(c[nl], a, B.x, B.y);
            }
        }

        // -- epilogue: leaky(c+b1) . w2 over this warp's 16 cols -> quad reduce --
        float p0 = 0.f, p1 = 0.f;      // rows g, g+8
        #pragma unroll
        for (int nl = 0; nl < 2; ++nl) {
            const int c0 = (wn * 2 + nl) * 8 + 2 * t;
            const float bb0 = b1s[c0], bb1 = b1s[c0 + 1];
            const float ww0 = w2s[c0], ww1 = w2s[c0 + 1];
            p0 += lk(c[nl][0] + bb0) * ww0 + lk(c[nl][1] + bb1) * ww1;
            p1 += lk(c[nl][2] + bb0) * ww0 + lk(c[nl][3] + bb1) * ww1;
        }
        p0 += __shfl_xor_sync(0xffffffffu, p0, 1);
        p0 += __shfl_xor_sync(0xffffffffu, p0, 2);
        p1 += __shfl_xor_sync(0xffffffffu, p1, 1);
        p1 += __shfl_xor_sync(0xffffffffu, p1, 2);

        if (t == 0 && wn == 1) {
            part[wm * 16 + g]     = p0;
            part[wm * 16 + 8 + g] = p1;
        }
        __syncthreads();   // partials visible; all reads of X buf[i&1] done
        if (t == 0 && wn == 0) {
            const int r = row0 + i * MT + wm * 16 + g;
            out[(size_t)r * Ee + e]       = lk(p0 + part[wm * 16 + g]     + bias2);
            out[(size_t)(r + 8) * Ee + e] = lk(p1 + part[wm * 16 + 8 + g] + bias2);
        }
    }
}

extern "C" void kernel_launch(void* const* d_in, const int* in_sizes, int n_in,
                              void* d_out, int out_size) {
    const float* x  = (const float*)d_in[0];
    const float* W1 = (const float*)d_in[1];
    const float* b1 = (const float*)d_in[2];
    const float* W2 = (const float*)d_in[3];
    const float* b2 = (const float*)d_in[4];
    float* out = (float*)d_out;

    const int B = in_sizes[0] / (Ee * Ee);           // 32768
    const int G = B / (MT * T);                      // 64 row-groups per expert
    const int grid = Ee * G;                         // 5760 CTAs
    const size_t smem = (size_t)(2 * XBUF + Hh * STR + 2 * Hh + MT) * sizeof(float); // 67072 B

    cudaFuncSetAttribute(sem_kernel, cudaFuncAttributeMaxDynamicSharedMemorySize, (int)smem);
    sem_kernel<<<grid, THREADS, smem>>>(x, W1, b1, W2, b2, out);
}